// round 1
// baseline (speedup 1.0000x reference)
#include <cuda_runtime.h>
#include <math.h>

#define B_      8
#define N_      1024
#define DIM_    768
#define H_      12
#define DH_     64
#define CTX_    992
#define BH_     (B_ * H_)     // 96
#define ROWS_   (B_ * N_)     // 8192

// ---------------- scratch (device globals; no allocation allowed) ----------
__device__ float g_Qflat [ROWS_ * DIM_];    // x @ Wq
__device__ float g_KVflat[ROWS_ * DIM_];    // x @ Wkv
__device__ float g_Qh    [BH_ * N_ * DH_];  // roped+scaled Q, head-major
__device__ float g_KVh   [BH_ * N_ * DH_];  // roped KV, head-major
__device__ float g_LKVh  [BH_ * N_ * DH_];  // LN(roped KV), head-major
__device__ float g_Attn  [ROWS_ * DIM_];    // merged attention output

// ---------------- GEMM: C[8192,768] = A[8192,768] @ W[768,768] -------------
// 64x64 tile, BK=16, 256 threads, 4x4 per thread.
__global__ __launch_bounds__(256) void sgemm_qkv(const float* __restrict__ A,
                                                 const float* __restrict__ Wm,
                                                 int which) {
    float* C = which ? g_KVflat : g_Qflat;
    __shared__ float As[16][65];   // [k][m], padded
    __shared__ float Bs[16][64];   // [k][n]

    const int m0 = blockIdx.x * 64;
    const int n0 = blockIdx.y * 64;
    const int tid = threadIdx.x;
    const int ty = tid >> 4;       // 0..15 (M dir)
    const int tx = tid & 15;       // 0..15 (N dir)

    const int lr = tid >> 2;       // 0..63 A row
    const int lc = tid & 3;        // 0..3  A float4 col
    const int bk = tid >> 4;       // 0..15 B k
    const int bc = tid & 15;       // 0..15 B float4 col

    float acc[4][4] = {};

    for (int k0 = 0; k0 < DIM_; k0 += 16) {
        float4 av = *(const float4*)(A  + (size_t)(m0 + lr) * DIM_ + k0 + lc * 4);
        float4 bv = *(const float4*)(Wm + (size_t)(k0 + bk) * DIM_ + n0 + bc * 4);
        __syncthreads();
        As[lc * 4 + 0][lr] = av.x;
        As[lc * 4 + 1][lr] = av.y;
        As[lc * 4 + 2][lr] = av.z;
        As[lc * 4 + 3][lr] = av.w;
        *(float4*)&Bs[bk][bc * 4] = bv;
        __syncthreads();

        #pragma unroll
        for (int kk = 0; kk < 16; kk++) {
            float a[4];
            #pragma unroll
            for (int i = 0; i < 4; i++) a[i] = As[kk][ty * 4 + i];
            float4 b4 = *(const float4*)&Bs[kk][tx * 4];
            #pragma unroll
            for (int i = 0; i < 4; i++) {
                acc[i][0] += a[i] * b4.x;
                acc[i][1] += a[i] * b4.y;
                acc[i][2] += a[i] * b4.z;
                acc[i][3] += a[i] * b4.w;
            }
        }
    }

    #pragma unroll
    for (int i = 0; i < 4; i++) {
        float4 v = make_float4(acc[i][0], acc[i][1], acc[i][2], acc[i][3]);
        *(float4*)(C + (size_t)(m0 + ty * 4 + i) * DIM_ + n0 + tx * 4) = v;
    }
}

// ---------------- RoPE on Q (+ 1/sqrt(DH) scale), head-major output --------
// warp per (bh, n) row; lane handles dims (lane, lane+32) == the rope pair.
__global__ __launch_bounds__(256) void rope_q_kernel() {
    int warp = (blockIdx.x * 256 + threadIdx.x) >> 5;
    int lane = threadIdx.x & 31;
    int bh = warp / N_, n = warp % N_;
    int b = bh / H_, h = bh % H_;
    const float* p = g_Qflat + ((size_t)(b * N_ + n)) * DIM_ + h * DH_;
    float t1 = p[lane], t2 = p[lane + 32];
    // inv = 10000^(-lane/32) ; log(10000)/32 = 0.28782313662425575
    float inv = expf(-(float)lane * 0.28782313662425575f);
    float fr = (float)n * inv;
    float sn, cs;
    sincosf(fr, &sn, &cs);
    float r1 = (t1 * cs - t2 * sn) * 0.125f;
    float r2 = (t2 * cs + t1 * sn) * 0.125f;
    size_t o = ((size_t)bh * N_ + n) * DH_;
    g_Qh[o + lane] = r1;
    g_Qh[o + lane + 32] = r2;
}

// ---------------- RoPE + LayerNorm on KV, head-major outputs ---------------
__global__ __launch_bounds__(256) void rope_ln_kv_kernel(const float* __restrict__ lng,
                                                         const float* __restrict__ lnb) {
    int warp = (blockIdx.x * 256 + threadIdx.x) >> 5;
    int lane = threadIdx.x & 31;
    int bh = warp / N_, n = warp % N_;
    int b = bh / H_, h = bh % H_;
    const float* p = g_KVflat + ((size_t)(b * N_ + n)) * DIM_ + h * DH_;
    float t1 = p[lane], t2 = p[lane + 32];
    float inv = expf(-(float)lane * 0.28782313662425575f);
    float fr = (float)n * inv;
    float sn, cs;
    sincosf(fr, &sn, &cs);
    float r1 = t1 * cs - t2 * sn;
    float r2 = t2 * cs + t1 * sn;
    size_t o = ((size_t)bh * N_ + n) * DH_;
    g_KVh[o + lane] = r1;
    g_KVh[o + lane + 32] = r2;

    float sum = r1 + r2;
    #pragma unroll
    for (int off = 16; off; off >>= 1) sum += __shfl_xor_sync(0xffffffffu, sum, off);
    float mean = sum * (1.0f / 64.0f);
    float d1 = r1 - mean, d2 = r2 - mean;
    float v = d1 * d1 + d2 * d2;
    #pragma unroll
    for (int off = 16; off; off >>= 1) v += __shfl_xor_sync(0xffffffffu, v, off);
    float istd = rsqrtf(v * (1.0f / 64.0f) + 1e-5f);
    g_LKVh[o + lane]      = d1 * istd * lng[lane]      + lnb[lane];
    g_LKVh[o + lane + 32] = d2 * istd * lng[lane + 32] + lnb[lane + 32];
}

// ---------------- Attention --------------------------------------------------
// Block = 128 queries (one thread per query), grid (BH, N/128).
// Scores q.kv over shared K tile; softmax without max-sub (logits are O(1):
// weights scaled 0.02, q scaled 1/8 -> |logit| < ~5, exp safe); ctx queries
// mask keys >= CTX. acc += p * LKV from shared V tile.
__global__ __launch_bounds__(128) void attn_kernel() {
    const int bh = blockIdx.x;
    const int qt = blockIdx.y;
    const int tid = threadIdx.x;
    const int qi = qt * 128 + tid;
    const bool is_lat = (qi >= CTX_);

    const float4* qp = (const float4*)(g_Qh + ((size_t)bh * N_ + qi) * DH_);
    float4 q4[16], acc4[16];
    #pragma unroll
    for (int i = 0; i < 16; i++) {
        q4[i] = qp[i];
        acc4[i] = make_float4(0.f, 0.f, 0.f, 0.f);
    }
    float l = 0.f;

    __shared__ float4 ksh[64 * 16];  // 64 keys x 16 float4
    __shared__ float4 vsh[64 * 16];

    for (int kt = 0; kt < 16; kt++) {
        const float4* kb = (const float4*)(g_KVh  + ((size_t)bh * N_ + kt * 64) * DH_);
        const float4* vb = (const float4*)(g_LKVh + ((size_t)bh * N_ + kt * 64) * DH_);
        __syncthreads();
        #pragma unroll
        for (int i = 0; i < 8; i++) {
            int idx = i * 128 + tid;
            ksh[idx] = kb[idx];
            vsh[idx] = vb[idx];
        }
        __syncthreads();

        #pragma unroll 4
        for (int j = 0; j < 64; j++) {
            float sx = 0.f, sy = 0.f, sz = 0.f, sw = 0.f;
            #pragma unroll
            for (int c = 0; c < 16; c++) {
                float4 k = ksh[j * 16 + c];
                sx += q4[c].x * k.x;
                sy += q4[c].y * k.y;
                sz += q4[c].z * k.z;
                sw += q4[c].w * k.w;
            }
            float s = (sx + sy) + (sz + sw);
            float p = __expf(s);
            if (!is_lat && (kt * 64 + j) >= CTX_) p = 0.f;
            l += p;
            #pragma unroll
            for (int c = 0; c < 16; c++) {
                float4 v = vsh[j * 16 + c];
                acc4[c].x += p * v.x;
                acc4[c].y += p * v.y;
                acc4[c].z += p * v.z;
                acc4[c].w += p * v.w;
            }
        }
    }

    float invl = 1.0f / l;
    int b = bh / H_, h = bh % H_;
    float4* op = (float4*)(g_Attn + ((size_t)(b * N_ + qi)) * DIM_ + h * DH_);
    #pragma unroll
    for (int c = 0; c < 16; c++) {
        float4 a = acc4[c];
        a.x *= invl; a.y *= invl; a.z *= invl; a.w *= invl;
        op[c] = a;
    }
}

// ---------------- Output projection: per-row W select + bias ----------------
// 32x64 tile (CTX=992 = 31*32 -> every tile homogeneous), BK=16, 256 threads,
// 2x4 per thread.
__global__ __launch_bounds__(256) void sgemm_out(const float* __restrict__ Wc,
                                                 const float* __restrict__ bc,
                                                 const float* __restrict__ Wl,
                                                 const float* __restrict__ bl,
                                                 float* __restrict__ C) {
    const int m0 = blockIdx.x * 32;
    const int n0 = blockIdx.y * 64;
    const int nloc = m0 % N_;
    const float* W    = (nloc < CTX_) ? Wc : Wl;
    const float* bias = (nloc < CTX_) ? bc : bl;

    __shared__ float As[16][33];
    __shared__ float Bs[16][64];

    const int tid = threadIdx.x;
    const int ty = tid >> 4;   // 0..15, rows ty*2..+1
    const int tx = tid & 15;   // cols tx*4..+3

    const int ar = tid >> 2;   // 0..63 (only <32 used for A)
    const int ac = tid & 3;
    const int bk = tid >> 4;
    const int bcc = tid & 15;

    float acc[2][4] = {};

    for (int k0 = 0; k0 < DIM_; k0 += 16) {
        float4 av = make_float4(0.f, 0.f, 0.f, 0.f);
        if (tid < 128)
            av = *(const float4*)(g_Attn + (size_t)(m0 + ar) * DIM_ + k0 + ac * 4);
        float4 bv = *(const float4*)(W + (size_t)(k0 + bk) * DIM_ + n0 + bcc * 4);
        __syncthreads();
        if (tid < 128) {
            As[ac * 4 + 0][ar] = av.x;
            As[ac * 4 + 1][ar] = av.y;
            As[ac * 4 + 2][ar] = av.z;
            As[ac * 4 + 3][ar] = av.w;
        }
        *(float4*)&Bs[bk][bcc * 4] = bv;
        __syncthreads();

        #pragma unroll
        for (int kk = 0; kk < 16; kk++) {
            float a0 = As[kk][ty * 2 + 0];
            float a1 = As[kk][ty * 2 + 1];
            float4 b4 = *(const float4*)&Bs[kk][tx * 4];
            acc[0][0] += a0 * b4.x; acc[0][1] += a0 * b4.y;
            acc[0][2] += a0 * b4.z; acc[0][3] += a0 * b4.w;
            acc[1][0] += a1 * b4.x; acc[1][1] += a1 * b4.y;
            acc[1][2] += a1 * b4.z; acc[1][3] += a1 * b4.w;
        }
    }

    float4 bb = *(const float4*)(bias + n0 + tx * 4);
    #pragma unroll
    for (int i = 0; i < 2; i++) {
        float4 v = make_float4(acc[i][0] + bb.x, acc[i][1] + bb.y,
                               acc[i][2] + bb.z, acc[i][3] + bb.w);
        *(float4*)(C + (size_t)(m0 + ty * 2 + i) * DIM_ + n0 + tx * 4) = v;
    }
}

// ---------------- launch -----------------------------------------------------
extern "C" void kernel_launch(void* const* d_in, const int* in_sizes, int n_in,
                              void* d_out, int out_size) {
    const float* x      = (const float*)d_in[0];
    const float* Wq     = (const float*)d_in[1];
    const float* Wkv    = (const float*)d_in[2];
    const float* Wo_ctx = (const float*)d_in[3];
    const float* bo_ctx = (const float*)d_in[4];
    const float* Wo_lat = (const float*)d_in[5];
    const float* bo_lat = (const float*)d_in[6];
    const float* ln_g   = (const float*)d_in[7];
    const float* ln_b   = (const float*)d_in[8];
    float* out = (float*)d_out;

    dim3 g1(ROWS_ / 64, DIM_ / 64);
    sgemm_qkv<<<g1, 256>>>(x, Wq, 0);
    sgemm_qkv<<<g1, 256>>>(x, Wkv, 1);

    int nwarp_blocks = (BH_ * N_) / 8;  // 8 warps per 256-thread block
    rope_q_kernel<<<nwarp_blocks, 256>>>();
    rope_ln_kv_kernel<<<nwarp_blocks, 256>>>(ln_g, ln_b);

    attn_kernel<<<dim3(BH_, N_ / 128), 128>>>();

    sgemm_out<<<dim3(ROWS_ / 32, DIM_ / 64), 256>>>(Wo_ctx, bo_ctx, Wo_lat, bo_lat, out);
}

// round 2
// speedup vs baseline: 1.5554x; 1.5554x over previous
#include <cuda_runtime.h>
#include <math.h>
#include <stdint.h>

#define B_    8
#define N_    1024
#define DIM_  768
#define H_    12
#define DH_   64
#define CTX_  992
#define BH_   96
#define ROWS_ 8192

// ---------------- scratch ----------------------------------------------------
__device__ float g_Qh  [BH_ * N_ * DH_];   // roped+scaled Q, head-major
__device__ float g_KVh [BH_ * N_ * DH_];   // roped KV, head-major
__device__ float g_LKVh[BH_ * N_ * DH_];   // LN(roped KV), head-major
__device__ float g_Attn[ROWS_ * DIM_];     // merged attention output

// ---------------- tf32 mma helpers ------------------------------------------
__device__ __forceinline__ uint32_t f2t(float x) {
    uint32_t r; asm("cvt.rna.tf32.f32 %0, %1;" : "=r"(r) : "f"(x)); return r;
}
__device__ __forceinline__ void mma8(float4& c, const uint32_t* a, const uint32_t* b) {
    asm volatile(
        "mma.sync.aligned.m16n8k8.row.col.f32.tf32.tf32.f32 "
        "{%0,%1,%2,%3}, {%4,%5,%6,%7}, {%8,%9}, {%0,%1,%2,%3};\n"
        : "+f"(c.x), "+f"(c.y), "+f"(c.z), "+f"(c.w)
        : "r"(a[0]), "r"(a[1]), "r"(a[2]), "r"(a[3]), "r"(b[0]), "r"(b[1]));
}

// ---------------- projection GEMM + fused RoPE(/LN) epilogue -----------------
// C[128,64] tile = x[128,768] @ W[768, head*64..+64]. grid (64, 12), 256 thr.
template<int IS_KV>
__global__ __launch_bounds__(256) void proj_kernel(const float* __restrict__ A,
                                                   const float* __restrict__ W,
                                                   const float* __restrict__ lng,
                                                   const float* __restrict__ lnb) {
    __shared__ union {
        struct { uint32_t As[128][33]; uint32_t Bs[32][65]; } in;
        float Csh[128][65];
    } sm;

    const int m0   = blockIdx.x * 128;
    const int head = blockIdx.y;
    const int n0   = head * 64;
    const int tid  = threadIdx.x;
    const int lane = tid & 31, wid = tid >> 5;
    const int wm   = (wid & 3) * 32;     // 4 warps along M
    const int wn   = (wid >> 2) * 32;    // 2 warps along N
    const int g    = lane >> 2, t = lane & 3;

    float4 acc[2][4];
    #pragma unroll
    for (int i = 0; i < 2; i++)
        #pragma unroll
        for (int j = 0; j < 4; j++) acc[i][j] = make_float4(0.f, 0.f, 0.f, 0.f);

    for (int k0 = 0; k0 < DIM_; k0 += 32) {
        __syncthreads();
        #pragma unroll
        for (int i = 0; i < 4; i++) {                    // A: 128x32
            int idx = tid + i * 256;
            int r = idx >> 3, c4 = (idx & 7) * 4;
            float4 v = *(const float4*)(A + (size_t)(m0 + r) * DIM_ + k0 + c4);
            sm.in.As[r][c4 + 0] = f2t(v.x);
            sm.in.As[r][c4 + 1] = f2t(v.y);
            sm.in.As[r][c4 + 2] = f2t(v.z);
            sm.in.As[r][c4 + 3] = f2t(v.w);
        }
        #pragma unroll
        for (int i = 0; i < 2; i++) {                    // B: 32x64
            int idx = tid + i * 256;
            int r = idx >> 4, c4 = (idx & 15) * 4;
            float4 v = *(const float4*)(W + (size_t)(k0 + r) * DIM_ + n0 + c4);
            sm.in.Bs[r][c4 + 0] = f2t(v.x);
            sm.in.Bs[r][c4 + 1] = f2t(v.y);
            sm.in.Bs[r][c4 + 2] = f2t(v.z);
            sm.in.Bs[r][c4 + 3] = f2t(v.w);
        }
        __syncthreads();

        #pragma unroll
        for (int kk = 0; kk < 4; kk++) {
            uint32_t a[2][4], b[4][2];
            #pragma unroll
            for (int mt = 0; mt < 2; mt++) {
                int r = wm + mt * 16;
                a[mt][0] = sm.in.As[r + g    ][kk * 8 + t];
                a[mt][1] = sm.in.As[r + g + 8][kk * 8 + t];
                a[mt][2] = sm.in.As[r + g    ][kk * 8 + t + 4];
                a[mt][3] = sm.in.As[r + g + 8][kk * 8 + t + 4];
            }
            #pragma unroll
            for (int j = 0; j < 4; j++) {
                b[j][0] = sm.in.Bs[kk * 8 + t    ][wn + j * 8 + g];
                b[j][1] = sm.in.Bs[kk * 8 + t + 4][wn + j * 8 + g];
            }
            #pragma unroll
            for (int mt = 0; mt < 2; mt++)
                #pragma unroll
                for (int j = 0; j < 4; j++) mma8(acc[mt][j], a[mt], b[j]);
        }
    }
    __syncthreads();

    // stage C tile
    #pragma unroll
    for (int mt = 0; mt < 2; mt++)
        #pragma unroll
        for (int j = 0; j < 4; j++) {
            int r = wm + mt * 16 + g, c = wn + j * 8 + 2 * t;
            sm.Csh[r    ][c] = acc[mt][j].x; sm.Csh[r    ][c + 1] = acc[mt][j].y;
            sm.Csh[r + 8][c] = acc[mt][j].z; sm.Csh[r + 8][c + 1] = acc[mt][j].w;
        }
    __syncthreads();

    // rope epilogue (pairs (d, d+32), d<32)
    #pragma unroll
    for (int i = 0; i < 16; i++) {
        int idx = tid + i * 256;                 // 0..4095
        int r = idx >> 5, d = idx & 31;
        float t1 = sm.Csh[r][d], t2 = sm.Csh[r][d + 32];
        int row = m0 + r;
        int bb = row >> 10, n = row & 1023;
        float inv = expf(-(float)d * 0.28782313662425575f);
        float fr = (float)n * inv;
        float sn, cs; sincosf(fr, &sn, &cs);
        float r1 = t1 * cs - t2 * sn;
        float r2 = t2 * cs + t1 * sn;
        size_t o = ((size_t)(bb * H_ + head) * N_ + n) * DH_;
        if (!IS_KV) {
            g_Qh[o + d]      = r1 * 0.125f;
            g_Qh[o + d + 32] = r2 * 0.125f;
        } else {
            g_KVh[o + d]      = r1;
            g_KVh[o + d + 32] = r2;
        }
    }

    if (IS_KV) {
        // write roped values back for the LN pass
        __syncthreads();
        #pragma unroll
        for (int i = 0; i < 16; i++) {
            int idx = tid + i * 256;
            int r = idx >> 5, d = idx & 31;
            int row = m0 + r;
            int bb = row >> 10, n = row & 1023;
            size_t o = ((size_t)(bb * H_ + head) * N_ + n) * DH_;
            sm.Csh[r][d]      = g_KVh[o + d];
            sm.Csh[r][d + 32] = g_KVh[o + d + 32];
        }
        __syncthreads();
        // warp per row: LN over 64 dims
        for (int rr = 0; rr < 16; rr++) {
            int r = wid * 16 + rr;
            float v1 = sm.Csh[r][lane], v2 = sm.Csh[r][lane + 32];
            float s = v1 + v2;
            #pragma unroll
            for (int off = 16; off; off >>= 1) s += __shfl_xor_sync(0xffffffffu, s, off);
            float mean = s * (1.0f / 64.0f);
            float d1 = v1 - mean, d2 = v2 - mean;
            float vv = d1 * d1 + d2 * d2;
            #pragma unroll
            for (int off = 16; off; off >>= 1) vv += __shfl_xor_sync(0xffffffffu, vv, off);
            float istd = rsqrtf(vv * (1.0f / 64.0f) + 1e-5f);
            int row = m0 + r;
            int bb = row >> 10, n = row & 1023;
            size_t o = ((size_t)(bb * H_ + head) * N_ + n) * DH_;
            g_LKVh[o + lane]      = d1 * istd * lng[lane]      + lnb[lane];
            g_LKVh[o + lane + 32] = d2 * istd * lng[lane + 32] + lnb[lane + 32];
        }
    }
}

// ---------------- fused attention (tf32 mma) ---------------------------------
// grid (96, 8), block 256 (8 warps), dynamic smem.
// layout (u32 units): QP[128][65] @0 (Q stage, then per-warp P), Ksh[64][65]
// @8320, VshT[64][65] @12480. total 16640 u32 = 66560 B.
#define QP(r, c)  dsm[(r) * 65 + (c)]
#define KS(r, c)  dsm[8320 + (r) * 65 + (c)]
#define VT(d, k)  dsm[12480 + (d) * 65 + (k)]

__global__ __launch_bounds__(256, 2) void attn_kernel() {
    extern __shared__ uint32_t dsm[];
    const int bh = blockIdx.x;
    const int qt = blockIdx.y;
    const int m0 = qt * 128;
    const int tid = threadIdx.x;
    const int lane = tid & 31, wid = tid >> 5;
    const int g = lane >> 2, t = lane & 3;
    const int wr = wid * 16;                  // warp's 16 query rows

    // stage Q (tf32)
    const float* qsrc = g_Qh + ((size_t)bh * N_ + m0) * DH_;
    #pragma unroll
    for (int i = 0; i < 8; i++) {
        int idx = tid + i * 256;              // 0..2047 float4s
        int r = idx >> 4, c4 = (idx & 15) * 4;
        float4 v = *(const float4*)(qsrc + (size_t)r * DH_ + c4);
        QP(r, c4 + 0) = f2t(v.x); QP(r, c4 + 1) = f2t(v.y);
        QP(r, c4 + 2) = f2t(v.z); QP(r, c4 + 3) = f2t(v.w);
    }
    __syncthreads();

    uint32_t qa[8][4];
    #pragma unroll
    for (int kk = 0; kk < 8; kk++) {
        qa[kk][0] = QP(wr + g,     kk * 8 + t);
        qa[kk][1] = QP(wr + g + 8, kk * 8 + t);
        qa[kk][2] = QP(wr + g,     kk * 8 + t + 4);
        qa[kk][3] = QP(wr + g + 8, kk * 8 + t + 4);
    }
    __syncthreads();          // everyone's Q frags loaded before QP is reused as P

    float4 o[8];
    #pragma unroll
    for (int j = 0; j < 8; j++) o[j] = make_float4(0.f, 0.f, 0.f, 0.f);
    float l0 = 0.f, l1 = 0.f;
    const int r0g = m0 + wr + g;              // global query row of c.x/c.y
    const bool lat0 = (r0g     >= CTX_);
    const bool lat1 = (r0g + 8 >= CTX_);

    for (int kt = 0; kt < 16; kt++) {
        const float* kb = g_KVh  + ((size_t)bh * N_ + kt * 64) * DH_;
        const float* vb = g_LKVh + ((size_t)bh * N_ + kt * 64) * DH_;
        #pragma unroll
        for (int i = 0; i < 4; i++) {
            int idx = tid + i * 256;          // 0..1023 float4s
            int r = idx >> 4, c4 = (idx & 15) * 4;
            float4 kv = *(const float4*)(kb + (size_t)r * DH_ + c4);
            KS(r, c4 + 0) = f2t(kv.x); KS(r, c4 + 1) = f2t(kv.y);
            KS(r, c4 + 2) = f2t(kv.z); KS(r, c4 + 3) = f2t(kv.w);
            float4 vv = *(const float4*)(vb + (size_t)r * DH_ + c4);
            VT(c4 + 0, r) = f2t(vv.x); VT(c4 + 1, r) = f2t(vv.y);
            VT(c4 + 2, r) = f2t(vv.z); VT(c4 + 3, r) = f2t(vv.w);
        }
        __syncthreads();

        // S = Q K^T for this 64-key tile, then exp -> P (warp-private rows)
        #pragma unroll
        for (int j = 0; j < 8; j++) {
            float4 s = make_float4(0.f, 0.f, 0.f, 0.f);
            #pragma unroll
            for (int kk = 0; kk < 8; kk++) {
                uint32_t b[2];
                b[0] = KS(j * 8 + g, kk * 8 + t);
                b[1] = KS(j * 8 + g, kk * 8 + t + 4);
                mma8(s, qa[kk], b);
            }
            float px = __expf(s.x), py = __expf(s.y);
            float pz = __expf(s.z), pw = __expf(s.w);
            if (kt == 15) {
                int kc = j * 8 + 2 * t;       // local key col (even)
                if (kc >= 32) {               // keys >= CTX_
                    if (!lat0) { px = 0.f; py = 0.f; }
                    if (!lat1) { pz = 0.f; pw = 0.f; }
                }
            }
            l0 += px + py; l1 += pz + pw;
            int c = j * 8 + 2 * t;
            QP(wr + g,     c) = f2t(px); QP(wr + g,     c + 1) = f2t(py);
            QP(wr + g + 8, c) = f2t(pz); QP(wr + g + 8, c + 1) = f2t(pw);
        }
        __syncwarp();

        // O += P V
        #pragma unroll
        for (int kk = 0; kk < 8; kk++) {
            uint32_t ap[4];
            ap[0] = QP(wr + g,     kk * 8 + t);
            ap[1] = QP(wr + g + 8, kk * 8 + t);
            ap[2] = QP(wr + g,     kk * 8 + t + 4);
            ap[3] = QP(wr + g + 8, kk * 8 + t + 4);
            #pragma unroll
            for (int j = 0; j < 8; j++) {
                uint32_t b[2];
                b[0] = VT(j * 8 + g, kk * 8 + t);
                b[1] = VT(j * 8 + g, kk * 8 + t + 4);
                mma8(o[j], ap, b);
            }
        }
        __syncthreads();
    }

    // rowsum reduce across the 4 lanes of each group
    l0 += __shfl_xor_sync(0xffffffffu, l0, 1);
    l0 += __shfl_xor_sync(0xffffffffu, l0, 2);
    l1 += __shfl_xor_sync(0xffffffffu, l1, 1);
    l1 += __shfl_xor_sync(0xffffffffu, l1, 2);
    float i0 = 1.0f / l0, i1 = 1.0f / l1;

    const int bb = bh / H_, h = bh % H_;
    #pragma unroll
    for (int j = 0; j < 8; j++) {
        int col = h * 64 + j * 8 + 2 * t;
        float* p0 = g_Attn + (size_t)(bb * N_ + r0g)     * DIM_ + col;
        float* p1 = g_Attn + (size_t)(bb * N_ + r0g + 8) * DIM_ + col;
        p0[0] = o[j].x * i0; p0[1] = o[j].y * i0;
        p1[0] = o[j].z * i1; p1[1] = o[j].w * i1;
    }
}

// ---------------- output projection (row-dependent W) ------------------------
// M tile 32 (992 = 31*32 -> homogeneous), N tile 128. grid (256, 6), 256 thr.
__global__ __launch_bounds__(256) void out_kernel(const float* __restrict__ Wc,
                                                  const float* __restrict__ bc,
                                                  const float* __restrict__ Wl,
                                                  const float* __restrict__ bl,
                                                  float* __restrict__ out) {
    __shared__ uint32_t As[32][33];
    __shared__ uint32_t Bs[32][129];

    const int m0 = blockIdx.x * 32;
    const int n0 = blockIdx.y * 128;
    const bool ctx = ((m0 & 1023) < CTX_);
    const float* W    = ctx ? Wc : Wl;
    const float* bias = ctx ? bc : bl;

    const int tid = threadIdx.x;
    const int lane = tid & 31, wid = tid >> 5;
    const int wm = (wid & 1) * 16;
    const int wn = (wid >> 1) * 32;
    const int g = lane >> 2, t = lane & 3;

    float4 acc[4];
    #pragma unroll
    for (int j = 0; j < 4; j++) acc[j] = make_float4(0.f, 0.f, 0.f, 0.f);

    for (int k0 = 0; k0 < DIM_; k0 += 32) {
        __syncthreads();
        {                                      // A: 32x32, 1 float4/thread
            int r = tid >> 3, c4 = (tid & 7) * 4;
            float4 v = *(const float4*)(g_Attn + (size_t)(m0 + r) * DIM_ + k0 + c4);
            As[r][c4 + 0] = f2t(v.x); As[r][c4 + 1] = f2t(v.y);
            As[r][c4 + 2] = f2t(v.z); As[r][c4 + 3] = f2t(v.w);
        }
        #pragma unroll
        for (int i = 0; i < 4; i++) {          // B: 32x128
            int idx = tid + i * 256;
            int r = idx >> 5, c4 = (idx & 31) * 4;
            float4 v = *(const float4*)(W + (size_t)(k0 + r) * DIM_ + n0 + c4);
            Bs[r][c4 + 0] = f2t(v.x); Bs[r][c4 + 1] = f2t(v.y);
            Bs[r][c4 + 2] = f2t(v.z); Bs[r][c4 + 3] = f2t(v.w);
        }
        __syncthreads();

        #pragma unroll
        for (int kk = 0; kk < 4; kk++) {
            uint32_t a[4];
            a[0] = As[wm + g    ][kk * 8 + t];
            a[1] = As[wm + g + 8][kk * 8 + t];
            a[2] = As[wm + g    ][kk * 8 + t + 4];
            a[3] = As[wm + g + 8][kk * 8 + t + 4];
            #pragma unroll
            for (int j = 0; j < 4; j++) {
                uint32_t b[2];
                b[0] = Bs[kk * 8 + t    ][wn + j * 8 + g];
                b[1] = Bs[kk * 8 + t + 4][wn + j * 8 + g];
                mma8(acc[j], a, b);
            }
        }
    }

    #pragma unroll
    for (int j = 0; j < 4; j++) {
        int col = n0 + wn + j * 8 + 2 * t;
        float bx = bias[col], by = bias[col + 1];
        int r0 = m0 + wm + g;
        out[(size_t)r0 * DIM_ + col]           = acc[j].x + bx;
        out[(size_t)r0 * DIM_ + col + 1]       = acc[j].y + by;
        out[(size_t)(r0 + 8) * DIM_ + col]     = acc[j].z + bx;
        out[(size_t)(r0 + 8) * DIM_ + col + 1] = acc[j].w + by;
    }
}

// ---------------- launch -----------------------------------------------------
extern "C" void kernel_launch(void* const* d_in, const int* in_sizes, int n_in,
                              void* d_out, int out_size) {
    const float* x      = (const float*)d_in[0];
    const float* Wq     = (const float*)d_in[1];
    const float* Wkv    = (const float*)d_in[2];
    const float* Wo_ctx = (const float*)d_in[3];
    const float* bo_ctx = (const float*)d_in[4];
    const float* Wo_lat = (const float*)d_in[5];
    const float* bo_lat = (const float*)d_in[6];
    const float* ln_g   = (const float*)d_in[7];
    const float* ln_b   = (const float*)d_in[8];
    float* out = (float*)d_out;

    cudaFuncSetAttribute(attn_kernel,
                         cudaFuncAttributeMaxDynamicSharedMemorySize, 66560);

    proj_kernel<0><<<dim3(64, 12), 256>>>(x, Wq, nullptr, nullptr);
    proj_kernel<1><<<dim3(64, 12), 256>>>(x, Wkv, ln_g, ln_b);
    attn_kernel<<<dim3(96, 8), 256, 66560>>>();
    out_kernel<<<dim3(256, 6), 256>>>(Wo_ctx, bo_ctx, Wo_lat, bo_lat, out);
}